// round 13
// baseline (speedup 1.0000x reference)
#include <cuda_runtime.h>
#include <cuda_bf16.h>
#include <cstdint>

// Problem constants
#define B_LON   15
#define NW      64
#define NTOK    144
#define DIM     192
#define NH      6
#define HD      32
#define MROWS   (B_LON * NW * NTOK)   // 138240
#define QKV_N   (3 * DIM)             // 576
#define NBIAS   3312
#define RB      72             // rows per attention CTA (half a window)

// Scratch (allocation-free rule: __device__ globals)
__device__ float g_qkv[(size_t)B_LON * NW * NTOK * QKV_N];   // 318 MB
__device__ float g_att[(size_t)B_LON * NW * NTOK * DIM];     // 106 MB
__device__ float g_biasT[(size_t)NW * NH * NBIAS];           // 5 MB: [w*NH+h][idx]

// ---------------------------------------------------------------------------
__global__ void bias_transpose_kernel(const float* __restrict__ bias_table,
                                      float* __restrict__ biasT)
{
    int idx = blockIdx.x;          // 0..3311
    int wh  = threadIdx.x;         // 0..383
    biasT[(size_t)wh * NBIAS + idx] = bias_table[(size_t)idx * (NW * NH) + wh];
}

// ---------------------------------------------------------------------------
// tf32 + cp.async helpers
// ---------------------------------------------------------------------------
__device__ __forceinline__ uint32_t f2tf32(float f) {
    uint32_t u;
    asm("cvt.rna.tf32.f32 %0, %1;" : "=r"(u) : "f"(f));
    return u;
}

__device__ __forceinline__ void mma_tf32(float* c, const uint32_t* a,
                                         const uint32_t* b) {
    asm volatile(
        "mma.sync.aligned.m16n8k8.row.col.f32.tf32.tf32.f32 "
        "{%0,%1,%2,%3}, {%4,%5,%6,%7}, {%8,%9}, {%0,%1,%2,%3};"
        : "+f"(c[0]), "+f"(c[1]), "+f"(c[2]), "+f"(c[3])
        : "r"(a[0]), "r"(a[1]), "r"(a[2]), "r"(a[3]),
          "r"(b[0]), "r"(b[1]));
}

__device__ __forceinline__ void cp16(void* dst, const void* src) {
    uint32_t s = (uint32_t)__cvta_generic_to_shared(dst);
    asm volatile("cp.async.cg.shared.global [%0], [%1], 16;" :: "r"(s), "l"(src));
}
__device__ __forceinline__ void cp_commit() {
    asm volatile("cp.async.commit_group;");
}
template <int N> __device__ __forceinline__ void cp_wait() {
    asm volatile("cp.async.wait_group %0;" :: "n"(N));
}
__device__ __forceinline__ void cp_wait_all() {
    asm volatile("cp.async.wait_all;");
}

// ---------------------------------------------------------------------------
// tf32 tensor-core GEMM + bias, 4-stage cp.async ring, ONE sync per K-tile.
// BM=128, BN=64, BK=16, 256 threads = 8 warps (4M x 2N), warp tile 32x32.
// Raw fp32 in smem; cvt.rna at fragment load. Dynamic smem 59.4KB, 3 CTAs/SM.
// Safety: prefetch at iter t writes buf (t+2)%4; slowest concurrent reader is
// at iter t-1 reading buf (t-1)%4; (t+2)-(t-1)=3 != 0 mod 4 -> no collision.
// ---------------------------------------------------------------------------
#define BM 128
#define BN 64
#define BK 16
#define AP 20
#define BP 72
#define NST 4
#define GEMM_SMEM_BYTES (NST * (BM * AP + BK * BP) * 4)

__global__ __launch_bounds__(256, 3) void gemm_tf32_kernel(
    const float* __restrict__ A, const float* __restrict__ B,
    const float* __restrict__ bias, float* __restrict__ C,
    int M, int N, int K)
{
    extern __shared__ float gsm[];
    float* As = gsm;                    // [NST][BM*AP]
    float* Bs = gsm + NST * BM * AP;    // [NST][BK*BP]

    const int tid  = threadIdx.x;
    const int lane = tid & 31;
    const int wid  = tid >> 5;
    const int wm   = wid & 3;
    const int wn   = wid >> 2;
    const int grp  = lane >> 2;
    const int tig  = lane & 3;

    const int m0 = blockIdx.y * BM;
    const int n0 = blockIdx.x * BN;

    // A staging: thread -> row ar (0..127), col ac (0 or 8), two 16B chunks
    const int ar = tid >> 1;
    const int ac = (tid & 1) * 8;
    const float* Ag = A + (size_t)(m0 + ar) * K + ac;
    // B staging: thread -> row bkr (0..15), col bnc, one 16B chunk
    const int bkr = tid >> 4;
    const int bnc = (tid & 15) * 4;
    const float* Bg = B + (size_t)bkr * N + n0 + bnc;

    float acc[2][4][4];
#pragma unroll
    for (int mi = 0; mi < 2; mi++)
#pragma unroll
        for (int ni = 0; ni < 4; ni++)
#pragma unroll
            for (int r = 0; r < 4; r++) acc[mi][ni][r] = 0.0f;

    const int T = K / BK;   // 12

    // Prologue: stage tiles 0 and 1
#pragma unroll
    for (int p = 0; p < 2; p++) {
        const float* a = Ag + p * BK;
        cp16(&As[p * BM * AP + ar * AP + ac],     a);
        cp16(&As[p * BM * AP + ar * AP + ac + 4], a + 4);
        cp16(&Bs[p * BK * BP + bkr * BP + bnc],   Bg + (size_t)p * BK * N);
        cp_commit();
    }

    for (int t = 0; t < T; t++) {
        if (t + 2 < T) {
            const int nb = (t + 2) % NST;
            const float* a = Ag + (t + 2) * BK;
            cp16(&As[nb * BM * AP + ar * AP + ac],     a);
            cp16(&As[nb * BM * AP + ar * AP + ac + 4], a + 4);
            cp16(&Bs[nb * BK * BP + bkr * BP + bnc],
                 Bg + (size_t)(t + 2) * BK * N);
            cp_commit();
            cp_wait<2>();
        } else {
            cp_wait<0>();
        }
        __syncthreads();   // the only barrier per iteration

        const float* Asb = As + (t % NST) * BM * AP;
        const float* Bsb = Bs + (t % NST) * BK * BP;
#pragma unroll
        for (int kc = 0; kc < BK; kc += 8) {
            uint32_t af[2][4], bf[4][2];
#pragma unroll
            for (int mi = 0; mi < 2; mi++) {
                int mb = wm * 32 + mi * 16 + grp;
                af[mi][0] = f2tf32(Asb[(mb)     * AP + kc + tig]);
                af[mi][1] = f2tf32(Asb[(mb + 8) * AP + kc + tig]);
                af[mi][2] = f2tf32(Asb[(mb)     * AP + kc + tig + 4]);
                af[mi][3] = f2tf32(Asb[(mb + 8) * AP + kc + tig + 4]);
            }
#pragma unroll
            for (int ni = 0; ni < 4; ni++) {
                int nb = wn * 32 + ni * 8 + grp;
                bf[ni][0] = f2tf32(Bsb[(kc + tig)     * BP + nb]);
                bf[ni][1] = f2tf32(Bsb[(kc + tig + 4) * BP + nb]);
            }
#pragma unroll
            for (int mi = 0; mi < 2; mi++)
#pragma unroll
                for (int ni = 0; ni < 4; ni++)
                    mma_tf32(acc[mi][ni], af[mi], bf[ni]);
        }
        // no trailing sync: NST=4 ring makes overwrite hazard impossible
    }

#pragma unroll
    for (int mi = 0; mi < 2; mi++) {
        int row = m0 + wm * 32 + mi * 16 + grp;
#pragma unroll
        for (int ni = 0; ni < 4; ni++) {
            int col = n0 + wn * 32 + ni * 8 + 2 * tig;
            float2 bv = *(const float2*)(bias + col);
            float2 o0, o1;
            o0.x = acc[mi][ni][0] + bv.x;
            o0.y = acc[mi][ni][1] + bv.y;
            o1.x = acc[mi][ni][2] + bv.x;
            o1.y = acc[mi][ni][3] + bv.y;
            *(float2*)(C + (size_t)row * N + col)       = o0;
            *(float2*)(C + (size_t)(row + 8) * N + col) = o1;
        }
    }
}

// ---------------------------------------------------------------------------
// Fused attention with tensor-core QK^T and PV (tf32 mma.m16n8k8).
// CTA = (b, w, h, rb): rows [rb*72, rb*72+72).
// q,k,bias staged via cp.async; v transposed+converted via registers.
// Mask is NOT pre-staged: softmax adds it from gmem (coalesced row LDG),
// so phase 2 waits only on q/k/bias. Scale folded into S epilogue.
// idx = f(n) + g(m): f = 828*zi + 23*hi + wi ; g = 1656*zj + 138*hj - wj + 11
// smem 105.7 KB -> 2 CTAs/SM.
// ---------------------------------------------------------------------------
#define QP 36     // qS pitch (f32)
#define KP 36     // kS pitch (f32)
#define VP 148    // vT pitch (u32/tf32)
#define SP 148    // S pitch (f32)

#define SM_QS    0                       // [80][36] f32 (rows 72..79 zero)
#define SM_KS    (SM_QS + 80 * QP)       // [144][36] f32
#define SM_VT    (SM_KS + NTOK * KP)     // [32][148] u32
#define SM_S     (SM_VT + 32 * VP)       // [72][148] f32
#define SM_BIAS  (SM_S + RB * SP)        // [3312] f32 (also phantom S rows)
#define SM_RSUM  (SM_BIAS + NBIAS)       // [72] f32
#define SM_FI    (SM_RSUM + RB)          // [72] int
#define SM_GI    (SM_FI + RB)            // [144] int
#define ATT_SMEM_BYTES ((SM_GI + NTOK) * 4)

__global__ __launch_bounds__(256, 2) void attn_kernel(
    const float* __restrict__ qkv, const float* __restrict__ mask,
    const float* __restrict__ biasT, float* __restrict__ out)
{
    extern __shared__ float sm[];
    float*    qSf  = sm + SM_QS;
    float*    kSf  = sm + SM_KS;
    uint32_t* vT   = (uint32_t*)sm + SM_VT;
    float*    S    = sm + SM_S;
    float*    sbias= sm + SM_BIAS;
    float*    rsum = sm + SM_RSUM;
    int*      fI   = (int*)sm + SM_FI;
    int*      gI   = (int*)sm + SM_GI;

    const int w = blockIdx.x, b = blockIdx.y;
    const int h  = blockIdx.z >> 1;
    const int rb = blockIdx.z & 1;
    const int tid  = threadIdx.x;
    const int lane = tid & 31;
    const int wp   = tid >> 5;          // 8 warps
    const int grp  = lane >> 2;         // 0..7
    const int tig  = lane & 3;          // 0..3
    const int bw = b * NW + w;
    const int row0 = rb * RB;
    const float* base = qkv + (size_t)bw * NTOK * QKV_N;
    const float* mbase = mask + (size_t)bw * NTOK * NTOK;
    const float scale = 0.17677669529663687f;  // 1/sqrt(32)

    // ---- cp.async staging: q (local 72 rows), k (all), bias slice
    for (int idx = tid; idx < RB * 8; idx += 256) {
        int r = idx >> 3, c = (idx & 7) * 4;
        cp16(&qSf[r * QP + c],
             base + (size_t)(row0 + r) * QKV_N + h * HD + c);
    }
    for (int idx = tid; idx < NTOK * 8; idx += 256) {
        int r = idx >> 3, c = (idx & 7) * 4;
        cp16(&kSf[r * KP + c],
             base + (size_t)r * QKV_N + DIM + h * HD + c);
    }
    {
        const float* bsrc = biasT + (size_t)(w * NH + h) * NBIAS;
        for (int i = tid * 4; i < NBIAS; i += 1024)
            cp16(&sbias[i], bsrc + i);
    }
    cp_commit();

    // ---- v: register path (transpose + tf32 convert), overlaps cp.async
    for (int idx = tid; idx < NTOK * 8; idx += 256) {
        int n = idx >> 3, d = (idx & 7) * 4;
        float4 v4 = *(const float4*)(base + (size_t)n * QKV_N + 2 * DIM
                                     + h * HD + d);
        vT[(d + 0) * VP + n] = f2tf32(v4.x);
        vT[(d + 1) * VP + n] = f2tf32(v4.y);
        vT[(d + 2) * VP + n] = f2tf32(v4.z);
        vT[(d + 3) * VP + n] = f2tf32(v4.w);
    }
    // qS pad rows 72..79 zero
    for (int i = tid; i < 8 * QP; i += 256) qSf[RB * QP + i] = 0.0f;
    if (tid < RB) {
        int n = row0 + tid;
        int zi = n / 72, hi = (n / 12) % 6, wi = n % 12;
        fI[tid] = 828 * zi + 23 * hi + wi;
    }
    if (tid < NTOK) {
        int zj = tid / 72, hj = (tid / 12) % 6, wj = tid % 12;
        gI[tid] = 1656 * zj + 138 * hj - wj + 11;
    }
    cp_wait_all();
    __syncthreads();

    // ---- Phase 2: S = scale*(q k^T) + bias via mma. 90 tiles (5m x 18n).
    for (int t = wp; t < 90; t += 8) {
        int m0 = (t / 18) * 16;
        int n0 = (t % 18) * 8;
        float c[4] = {0.0f, 0.0f, 0.0f, 0.0f};
#pragma unroll
        for (int kc = 0; kc < HD; kc += 8) {
            uint32_t a[4], bfr[2];
            int ab = (m0 + grp) * QP + kc + tig;
            a[0] = f2tf32(qSf[ab]);
            a[1] = f2tf32(qSf[ab + 8 * QP]);
            a[2] = f2tf32(qSf[ab + 4]);
            a[3] = f2tf32(qSf[ab + 8 * QP + 4]);
            int bb = (n0 + grp) * KP + kc + tig;
            bfr[0] = f2tf32(kSf[bb]);
            bfr[1] = f2tf32(kSf[bb + 4]);
            mma_tf32(c, a, bfr);
        }
        int col = n0 + 2 * tig;
        int g0 = gI[col], g1 = gI[col + 1];
#pragma unroll
        for (int p = 0; p < 2; p++) {
            int r = m0 + grp + p * 8;
            if (r < RB) {
                int f = fI[r];
                float* sr = S + r * SP + col;
                sr[0] = fmaf(c[2 * p],     scale, sbias[f + g0]);
                sr[1] = fmaf(c[2 * p + 1], scale, sbias[f + g1]);
            }
        }
    }
    __syncthreads();

    // ---- Phase 3: softmax with mask added from gmem (coalesced).
    // Warp wp owns rows wp*9..wp*9+8.
    {
#pragma unroll
        for (int i = 0; i < 9; i++) {
            int r = wp * 9 + i;
            float* row = S + r * SP;
            const float* mrow = mbase + (size_t)(row0 + r) * NTOK;
            float v0 = row[lane]       + mrow[lane];
            float v1 = row[lane + 32]  + mrow[lane + 32];
            float v2 = row[lane + 64]  + mrow[lane + 64];
            float v3 = row[lane + 96]  + mrow[lane + 96];
            float v4 = (lane < 16) ? row[lane + 128] + mrow[lane + 128]
                                   : -1e30f;
            float mx = fmaxf(fmaxf(fmaxf(v0, v1), fmaxf(v2, v3)), v4);
#pragma unroll
            for (int off = 16; off > 0; off >>= 1)
                mx = fmaxf(mx, __shfl_xor_sync(0xffffffffu, mx, off));
            float e0 = __expf(v0 - mx);
            float e1 = __expf(v1 - mx);
            float e2 = __expf(v2 - mx);
            float e3 = __expf(v3 - mx);
            float e4 = (lane < 16) ? __expf(v4 - mx) : 0.0f;
            row[lane]       = e0;
            row[lane + 32]  = e1;
            row[lane + 64]  = e2;
            row[lane + 96]  = e3;
            if (lane < 16) row[lane + 128] = e4;
            float s = (e0 + e1) + (e2 + e3) + e4;
#pragma unroll
            for (int off = 16; off > 0; off >>= 1)
                s += __shfl_xor_sync(0xffffffffu, s, off);
            if (lane == 0) rsum[r] = 1.0f / s;
        }
    }
    __syncthreads();

    // ---- Phase 4: O = P v via mma. 20 tiles (5m x 4n), K=144.
    // Phantom A rows (72..79) read into the bias region: in-bounds garbage,
    // contaminates only guarded (discarded) output rows.
    float* ob0 = out + (size_t)bw * NTOK * DIM + h * HD;
    for (int t = wp; t < 20; t += 8) {
        int m0 = (t >> 2) * 16;
        int n0 = (t & 3) * 8;
        float c[4] = {0.0f, 0.0f, 0.0f, 0.0f};
#pragma unroll 6
        for (int kc = 0; kc < NTOK; kc += 8) {
            uint32_t a[4], bfr[2];
            const float* ap = S + (m0 + grp) * SP + kc + tig;
            a[0] = f2tf32(ap[0]);
            a[1] = f2tf32(ap[8 * SP]);
            a[2] = f2tf32(ap[4]);
            a[3] = f2tf32(ap[8 * SP + 4]);
            int bb = (n0 + grp) * VP + kc + tig;
            bfr[0] = vT[bb];
            bfr[1] = vT[bb + 4];
            mma_tf32(c, a, bfr);
        }
        int col = n0 + 2 * tig;
#pragma unroll
        for (int p = 0; p < 2; p++) {
            int r = m0 + grp + p * 8;
            if (r < RB) {
                float rs = rsum[r];
                float2 o;
                o.x = c[2 * p] * rs;
                o.y = c[2 * p + 1] * rs;
                *(float2*)(ob0 + (size_t)(row0 + r) * DIM + col) = o;
            }
        }
    }
}

// ---------------------------------------------------------------------------
extern "C" void kernel_launch(void* const* d_in, const int* in_sizes, int n_in,
                              void* d_out, int out_size)
{
    const float* x          = (const float*)d_in[0];
    const float* mask       = (const float*)d_in[1];
    const float* qkv_w      = (const float*)d_in[2];
    const float* qkv_b      = (const float*)d_in[3];
    const float* proj_w     = (const float*)d_in[4];
    const float* proj_b     = (const float*)d_in[5];
    const float* bias_table = (const float*)d_in[6];
    float* out = (float*)d_out;

    float *qkv_s, *att_s, *biasT_s;
    cudaGetSymbolAddress((void**)&qkv_s, g_qkv);
    cudaGetSymbolAddress((void**)&att_s, g_att);
    cudaGetSymbolAddress((void**)&biasT_s, g_biasT);

    cudaFuncSetAttribute(gemm_tf32_kernel,
                         cudaFuncAttributeMaxDynamicSharedMemorySize,
                         GEMM_SMEM_BYTES);
    cudaFuncSetAttribute(attn_kernel,
                         cudaFuncAttributeMaxDynamicSharedMemorySize,
                         ATT_SMEM_BYTES);

    // 0) Bias table pre-transpose (tiny)
    bias_transpose_kernel<<<NBIAS, NW * NH>>>(bias_table, biasT_s);

    // 1) QKV projection: (138240 x 192) @ (192 x 576) + b   [tf32 tensor]
    gemm_tf32_kernel<<<dim3(QKV_N / BN, MROWS / BM), 256, GEMM_SMEM_BYTES>>>(
        x, qkv_w, qkv_b, qkv_s, MROWS, QKV_N, DIM);

    // 2) Fused windowed attention per (w, b, h, row-half)   [tf32 tensor]
    attn_kernel<<<dim3(NW, B_LON, NH * 2), 256, ATT_SMEM_BYTES>>>(
        qkv_s, mask, biasT_s, att_s);

    // 3) Output projection: (138240 x 192) @ (192 x 192) + b [tf32 tensor]
    gemm_tf32_kernel<<<dim3(DIM / BN, MROWS / BM), 256, GEMM_SMEM_BYTES>>>(
        att_s, proj_w, proj_b, out, MROWS, DIM, DIM);
}

// round 14
// speedup vs baseline: 1.0423x; 1.0423x over previous
#include <cuda_runtime.h>
#include <cuda_bf16.h>
#include <cstdint>

// Problem constants
#define B_LON   15
#define NW      64
#define NTOK    144
#define DIM     192
#define NH      6
#define HD      32
#define MROWS   (B_LON * NW * NTOK)   // 138240
#define QKV_N   (3 * DIM)             // 576
#define NBIAS   3312
#define RB      72             // rows per attention CTA (half a window)

// Scratch (allocation-free rule: __device__ globals)
__device__ float g_qkv[(size_t)B_LON * NW * NTOK * QKV_N];   // 318 MB
__device__ float g_att[(size_t)B_LON * NW * NTOK * DIM];     // 106 MB
__device__ float g_biasT[(size_t)NW * NH * NBIAS];           // 5 MB: [w*NH+h][idx]

// ---------------------------------------------------------------------------
__global__ void bias_transpose_kernel(const float* __restrict__ bias_table,
                                      float* __restrict__ biasT)
{
    int idx = blockIdx.x;          // 0..3311
    int wh  = threadIdx.x;         // 0..383
    biasT[(size_t)wh * NBIAS + idx] = bias_table[(size_t)idx * (NW * NH) + wh];
}

// ---------------------------------------------------------------------------
// tf32 + cp.async helpers
// ---------------------------------------------------------------------------
__device__ __forceinline__ uint32_t f2tf32(float f) {
    uint32_t u;
    asm("cvt.rna.tf32.f32 %0, %1;" : "=r"(u) : "f"(f));
    return u;
}

__device__ __forceinline__ void mma_tf32(float* c, const uint32_t* a,
                                         const uint32_t* b) {
    asm volatile(
        "mma.sync.aligned.m16n8k8.row.col.f32.tf32.tf32.f32 "
        "{%0,%1,%2,%3}, {%4,%5,%6,%7}, {%8,%9}, {%0,%1,%2,%3};"
        : "+f"(c[0]), "+f"(c[1]), "+f"(c[2]), "+f"(c[3])
        : "r"(a[0]), "r"(a[1]), "r"(a[2]), "r"(a[3]),
          "r"(b[0]), "r"(b[1]));
}

__device__ __forceinline__ void cp16(void* dst, const void* src) {
    uint32_t s = (uint32_t)__cvta_generic_to_shared(dst);
    asm volatile("cp.async.cg.shared.global [%0], [%1], 16;" :: "r"(s), "l"(src));
}
__device__ __forceinline__ void cp_commit() {
    asm volatile("cp.async.commit_group;");
}
template <int N> __device__ __forceinline__ void cp_wait() {
    asm volatile("cp.async.wait_group %0;" :: "n"(N));
}
__device__ __forceinline__ void cp_wait_all() {
    asm volatile("cp.async.wait_all;");
}

// ---------------------------------------------------------------------------
// tf32 tensor-core GEMM + bias, 4-stage cp.async ring, ONE sync per K-tile.
// (unchanged from round 9 — profiled good)
// ---------------------------------------------------------------------------
#define BM 128
#define BN 64
#define BK 16
#define AP 20
#define BP 72
#define NST 4
#define GEMM_SMEM_BYTES (NST * (BM * AP + BK * BP) * 4)

__global__ __launch_bounds__(256, 3) void gemm_tf32_kernel(
    const float* __restrict__ A, const float* __restrict__ B,
    const float* __restrict__ bias, float* __restrict__ C,
    int M, int N, int K)
{
    extern __shared__ float gsm[];
    float* As = gsm;                    // [NST][BM*AP]
    float* Bs = gsm + NST * BM * AP;    // [NST][BK*BP]

    const int tid  = threadIdx.x;
    const int lane = tid & 31;
    const int wid  = tid >> 5;
    const int wm   = wid & 3;
    const int wn   = wid >> 2;
    const int grp  = lane >> 2;
    const int tig  = lane & 3;

    const int m0 = blockIdx.y * BM;
    const int n0 = blockIdx.x * BN;

    const int ar = tid >> 1;
    const int ac = (tid & 1) * 8;
    const float* Ag = A + (size_t)(m0 + ar) * K + ac;
    const int bkr = tid >> 4;
    const int bnc = (tid & 15) * 4;
    const float* Bg = B + (size_t)bkr * N + n0 + bnc;

    float acc[2][4][4];
#pragma unroll
    for (int mi = 0; mi < 2; mi++)
#pragma unroll
        for (int ni = 0; ni < 4; ni++)
#pragma unroll
            for (int r = 0; r < 4; r++) acc[mi][ni][r] = 0.0f;

    const int T = K / BK;   // 12

#pragma unroll
    for (int p = 0; p < 2; p++) {
        const float* a = Ag + p * BK;
        cp16(&As[p * BM * AP + ar * AP + ac],     a);
        cp16(&As[p * BM * AP + ar * AP + ac + 4], a + 4);
        cp16(&Bs[p * BK * BP + bkr * BP + bnc],   Bg + (size_t)p * BK * N);
        cp_commit();
    }

    for (int t = 0; t < T; t++) {
        if (t + 2 < T) {
            const int nb = (t + 2) % NST;
            const float* a = Ag + (t + 2) * BK;
            cp16(&As[nb * BM * AP + ar * AP + ac],     a);
            cp16(&As[nb * BM * AP + ar * AP + ac + 4], a + 4);
            cp16(&Bs[nb * BK * BP + bkr * BP + bnc],
                 Bg + (size_t)(t + 2) * BK * N);
            cp_commit();
            cp_wait<2>();
        } else {
            cp_wait<0>();
        }
        __syncthreads();

        const float* Asb = As + (t % NST) * BM * AP;
        const float* Bsb = Bs + (t % NST) * BK * BP;
#pragma unroll
        for (int kc = 0; kc < BK; kc += 8) {
            uint32_t af[2][4], bf[4][2];
#pragma unroll
            for (int mi = 0; mi < 2; mi++) {
                int mb = wm * 32 + mi * 16 + grp;
                af[mi][0] = f2tf32(Asb[(mb)     * AP + kc + tig]);
                af[mi][1] = f2tf32(Asb[(mb + 8) * AP + kc + tig]);
                af[mi][2] = f2tf32(Asb[(mb)     * AP + kc + tig + 4]);
                af[mi][3] = f2tf32(Asb[(mb + 8) * AP + kc + tig + 4]);
            }
#pragma unroll
            for (int ni = 0; ni < 4; ni++) {
                int nb = wn * 32 + ni * 8 + grp;
                bf[ni][0] = f2tf32(Bsb[(kc + tig)     * BP + nb]);
                bf[ni][1] = f2tf32(Bsb[(kc + tig + 4) * BP + nb]);
            }
#pragma unroll
            for (int mi = 0; mi < 2; mi++)
#pragma unroll
                for (int ni = 0; ni < 4; ni++)
                    mma_tf32(acc[mi][ni], af[mi], bf[ni]);
        }
    }

#pragma unroll
    for (int mi = 0; mi < 2; mi++) {
        int row = m0 + wm * 32 + mi * 16 + grp;
#pragma unroll
        for (int ni = 0; ni < 4; ni++) {
            int col = n0 + wn * 32 + ni * 8 + 2 * tig;
            float2 bv = *(const float2*)(bias + col);
            float2 o0, o1;
            o0.x = acc[mi][ni][0] + bv.x;
            o0.y = acc[mi][ni][1] + bv.y;
            o1.x = acc[mi][ni][2] + bv.x;
            o1.y = acc[mi][ni][3] + bv.y;
            *(float2*)(C + (size_t)row * N + col)       = o0;
            *(float2*)(C + (size_t)(row + 8) * N + col) = o1;
        }
    }
}

// ---------------------------------------------------------------------------
// Fused attention, tensor-core QK^T and PV, pre-converted tf32 operands.
// CTA = (b, w, h, rb): rows [rb*72, rb*72+72).
// Staging: q/k/bias cp.async (raw fp32), v register-transposed to tf32.
// Repack pass converts q (x scale) and k to tf32 in place -> phases 2/4
// load raw u32 fragments (no cvt in hot loops). Softmax stores P as tf32
// bits. Phase 2: m-block outer, hoisted a-frags. Phase 4: fixed n-tile per
// warp, hoisted v-frags (36 regs).
// idx = f(n) + g(m): f = 828*zi + 23*hi + wi ; g = 1656*zj + 138*hj - wj + 11
// smem 105.7 KB -> 2 CTAs/SM.
// ---------------------------------------------------------------------------
#define QP 36     // qS pitch
#define KP 36     // kS pitch
#define VP 148    // vT pitch
#define SP 148    // S pitch

#define SM_QS    0                       // [80][36] (rows 72..79 zero)
#define SM_KS    (SM_QS + 80 * QP)       // [144][36]
#define SM_VT    (SM_KS + NTOK * KP)     // [32][148] u32 tf32
#define SM_S     (SM_VT + 32 * VP)       // [72][148]
#define SM_BIAS  (SM_S + RB * SP)        // [3312] (also phantom S rows)
#define SM_RSUM  (SM_BIAS + NBIAS)       // [72]
#define SM_FI    (SM_RSUM + RB)          // [72] int
#define SM_GI    (SM_FI + RB)            // [144] int
#define ATT_SMEM_BYTES ((SM_GI + NTOK) * 4)

__global__ __launch_bounds__(256, 2) void attn_kernel(
    const float* __restrict__ qkv, const float* __restrict__ mask,
    const float* __restrict__ biasT, float* __restrict__ out)
{
    extern __shared__ float sm[];
    float*    qSf  = sm + SM_QS;
    float*    kSf  = sm + SM_KS;
    uint32_t* qSu  = (uint32_t*)qSf;
    uint32_t* kSu  = (uint32_t*)kSf;
    uint32_t* vT   = (uint32_t*)sm + SM_VT;
    float*    S    = sm + SM_S;
    uint32_t* Su   = (uint32_t*)S;
    float*    sbias= sm + SM_BIAS;
    float*    rsum = sm + SM_RSUM;
    int*      fI   = (int*)sm + SM_FI;
    int*      gI   = (int*)sm + SM_GI;

    const int w = blockIdx.x, b = blockIdx.y;
    const int h  = blockIdx.z >> 1;
    const int rb = blockIdx.z & 1;
    const int tid  = threadIdx.x;
    const int lane = tid & 31;
    const int wp   = tid >> 5;          // 8 warps
    const int grp  = lane >> 2;         // 0..7
    const int tig  = lane & 3;          // 0..3
    const int bw = b * NW + w;
    const int row0 = rb * RB;
    const float* base = qkv + (size_t)bw * NTOK * QKV_N;
    const float* mbase = mask + (size_t)bw * NTOK * NTOK;
    const float scale = 0.17677669529663687f;  // 1/sqrt(32)

    // ---- cp.async staging: q (local 72 rows), k (all), bias slice
    for (int idx = tid; idx < RB * 8; idx += 256) {
        int r = idx >> 3, c = (idx & 7) * 4;
        cp16(&qSf[r * QP + c],
             base + (size_t)(row0 + r) * QKV_N + h * HD + c);
    }
    for (int idx = tid; idx < NTOK * 8; idx += 256) {
        int r = idx >> 3, c = (idx & 7) * 4;
        cp16(&kSf[r * KP + c],
             base + (size_t)r * QKV_N + DIM + h * HD + c);
    }
    {
        const float* bsrc = biasT + (size_t)(w * NH + h) * NBIAS;
        for (int i = tid * 4; i < NBIAS; i += 1024)
            cp16(&sbias[i], bsrc + i);
    }
    cp_commit();

    // ---- v: register path (transpose + tf32 convert), overlaps cp.async
    for (int idx = tid; idx < NTOK * 8; idx += 256) {
        int n = idx >> 3, d = (idx & 7) * 4;
        float4 v4 = *(const float4*)(base + (size_t)n * QKV_N + 2 * DIM
                                     + h * HD + d);
        vT[(d + 0) * VP + n] = f2tf32(v4.x);
        vT[(d + 1) * VP + n] = f2tf32(v4.y);
        vT[(d + 2) * VP + n] = f2tf32(v4.z);
        vT[(d + 3) * VP + n] = f2tf32(v4.w);
    }
    // qS pad rows 72..79 zero
    for (int i = tid; i < 8 * QP; i += 256) qSf[RB * QP + i] = 0.0f;
    if (tid < RB) {
        int n = row0 + tid;
        int zi = n / 72, hi = (n / 12) % 6, wi = n % 12;
        fI[tid] = 828 * zi + 23 * hi + wi;
    }
    if (tid < NTOK) {
        int zj = tid / 72, hj = (tid / 12) % 6, wj = tid % 12;
        gI[tid] = 1656 * zj + 138 * hj - wj + 11;
    }
    cp_wait_all();
    __syncthreads();

    // ---- Repack: q (x scale) and k fp32 -> tf32 bits, in place.
    // Each element is read+written by exactly one thread.
    for (int i = tid; i < 80 * QP; i += 256) qSu[i] = f2tf32(qSf[i] * scale);
    for (int i = tid; i < NTOK * KP; i += 256) kSu[i] = f2tf32(kSf[i]);
    __syncthreads();

    // ---- Phase 2: S = (scaled q) k^T + bias via mma.
    // m-block outer (a-frags hoisted, 16 regs), rotated n-tile round-robin.
#pragma unroll
    for (int mb = 0; mb < 5; mb++) {
        uint32_t a[4][4];
#pragma unroll
        for (int kc8 = 0; kc8 < 4; kc8++) {
            int ab = (mb * 16 + grp) * QP + kc8 * 8 + tig;
            a[kc8][0] = qSu[ab];
            a[kc8][1] = qSu[ab + 8 * QP];
            a[kc8][2] = qSu[ab + 4];
            a[kc8][3] = qSu[ab + 8 * QP + 4];
        }
        int start = (wp + mb) & 7;           // rotate for load balance
        for (int nt = start; nt < 18; nt += 8) {
            float c[4] = {0.0f, 0.0f, 0.0f, 0.0f};
#pragma unroll
            for (int kc8 = 0; kc8 < 4; kc8++) {
                uint32_t bfr[2];
                int bb = (nt * 8 + grp) * KP + kc8 * 8 + tig;
                bfr[0] = kSu[bb];
                bfr[1] = kSu[bb + 4];
                mma_tf32(c, a[kc8], bfr);
            }
            int col = nt * 8 + 2 * tig;
            int g0 = gI[col], g1 = gI[col + 1];
#pragma unroll
            for (int p = 0; p < 2; p++) {
                int r = mb * 16 + grp + p * 8;
                if (r < RB) {
                    int f = fI[r];
                    float* sr = S + r * SP + col;
                    sr[0] = c[2 * p]     + sbias[f + g0];
                    sr[1] = c[2 * p + 1] + sbias[f + g1];
                }
            }
        }
    }
    __syncthreads();

    // ---- Phase 3: softmax with mask from gmem; store P as tf32 bits.
    {
#pragma unroll
        for (int i = 0; i < 9; i++) {
            int r = wp * 9 + i;
            float* row = S + r * SP;
            const float* mrow = mbase + (size_t)(row0 + r) * NTOK;
            float v0 = row[lane]       + mrow[lane];
            float v1 = row[lane + 32]  + mrow[lane + 32];
            float v2 = row[lane + 64]  + mrow[lane + 64];
            float v3 = row[lane + 96]  + mrow[lane + 96];
            float v4 = (lane < 16) ? row[lane + 128] + mrow[lane + 128]
                                   : -1e30f;
            float mx = fmaxf(fmaxf(fmaxf(v0, v1), fmaxf(v2, v3)), v4);
#pragma unroll
            for (int off = 16; off > 0; off >>= 1)
                mx = fmaxf(mx, __shfl_xor_sync(0xffffffffu, mx, off));
            float e0 = __expf(v0 - mx);
            float e1 = __expf(v1 - mx);
            float e2 = __expf(v2 - mx);
            float e3 = __expf(v3 - mx);
            float e4 = (lane < 16) ? __expf(v4 - mx) : 0.0f;
            uint32_t* rowu = (uint32_t*)row;
            rowu[lane]       = f2tf32(e0);
            rowu[lane + 32]  = f2tf32(e1);
            rowu[lane + 64]  = f2tf32(e2);
            rowu[lane + 96]  = f2tf32(e3);
            if (lane < 16) rowu[lane + 128] = f2tf32(e4);
            float s = (e0 + e1) + (e2 + e3) + e4;
#pragma unroll
            for (int off = 16; off > 0; off >>= 1)
                s += __shfl_xor_sync(0xffffffffu, s, off);
            if (lane == 0) rsum[r] = 1.0f / s;
        }
    }
    __syncthreads();

    // ---- Phase 4: O = P v via mma. Warp wp: fixed n-tile (wp&3),
    // m-blocks (wp>>2), +2, +4. v-frags hoisted (36 regs), reused per mb.
    // Phantom A rows 72..79 read the bias region: in-bounds, finite-bit
    // garbage, contaminates only guarded (discarded) output rows.
    {
        const int nt = wp & 3;
        uint32_t bf[18][2];
#pragma unroll
        for (int kc8 = 0; kc8 < 18; kc8++) {
            int bb = (nt * 8 + grp) * VP + kc8 * 8 + tig;
            bf[kc8][0] = vT[bb];
            bf[kc8][1] = vT[bb + 4];
        }
        float* ob0 = out + (size_t)bw * NTOK * DIM + h * HD;
        for (int mb = (wp >> 2); mb < 5; mb += 2) {
            float c[4] = {0.0f, 0.0f, 0.0f, 0.0f};
#pragma unroll
            for (int kc8 = 0; kc8 < 18; kc8++) {
                uint32_t a[4];
                int ab = (mb * 16 + grp) * SP + kc8 * 8 + tig;
                a[0] = Su[ab];
                a[1] = Su[ab + 8 * SP];
                a[2] = Su[ab + 4];
                a[3] = Su[ab + 8 * SP + 4];
                mma_tf32(c, a, bf[kc8]);
            }
            int col = nt * 8 + 2 * tig;
#pragma unroll
            for (int p = 0; p < 2; p++) {
                int r = mb * 16 + grp + p * 8;
                if (r < RB) {
                    float rs = rsum[r];
                    float2 o;
                    o.x = c[2 * p] * rs;
                    o.y = c[2 * p + 1] * rs;
                    *(float2*)(ob0 + (size_t)(row0 + r) * DIM + col) = o;
                }
            }
        }
    }
}

// ---------------------------------------------------------------------------
extern "C" void kernel_launch(void* const* d_in, const int* in_sizes, int n_in,
                              void* d_out, int out_size)
{
    const float* x          = (const float*)d_in[0];
    const float* mask       = (const float*)d_in[1];
    const float* qkv_w      = (const float*)d_in[2];
    const float* qkv_b      = (const float*)d_in[3];
    const float* proj_w     = (const float*)d_in[4];
    const float* proj_b     = (const float*)d_in[5];
    const float* bias_table = (const float*)d_in[6];
    float* out = (float*)d_out;

    float *qkv_s, *att_s, *biasT_s;
    cudaGetSymbolAddress((void**)&qkv_s, g_qkv);
    cudaGetSymbolAddress((void**)&att_s, g_att);
    cudaGetSymbolAddress((void**)&biasT_s, g_biasT);

    cudaFuncSetAttribute(gemm_tf32_kernel,
                         cudaFuncAttributeMaxDynamicSharedMemorySize,
                         GEMM_SMEM_BYTES);
    cudaFuncSetAttribute(attn_kernel,
                         cudaFuncAttributeMaxDynamicSharedMemorySize,
                         ATT_SMEM_BYTES);

    // 0) Bias table pre-transpose (tiny)
    bias_transpose_kernel<<<NBIAS, NW * NH>>>(bias_table, biasT_s);

    // 1) QKV projection: (138240 x 192) @ (192 x 576) + b   [tf32 tensor]
    gemm_tf32_kernel<<<dim3(QKV_N / BN, MROWS / BM), 256, GEMM_SMEM_BYTES>>>(
        x, qkv_w, qkv_b, qkv_s, MROWS, QKV_N, DIM);

    // 2) Fused windowed attention per (w, b, h, row-half)   [tf32 tensor]
    attn_kernel<<<dim3(NW, B_LON, NH * 2), 256, ATT_SMEM_BYTES>>>(
        qkv_s, mask, biasT_s, att_s);

    // 3) Output projection: (138240 x 192) @ (192 x 192) + b [tf32 tensor]
    gemm_tf32_kernel<<<dim3(DIM / BN, MROWS / BM), 256, GEMM_SMEM_BYTES>>>(
        att_s, proj_w, proj_b, out, MROWS, DIM, DIM);
}

// round 15
// speedup vs baseline: 1.1087x; 1.0637x over previous
#include <cuda_runtime.h>
#include <cuda_bf16.h>
#include <cstdint>

// Problem constants
#define B_LON   15
#define NW      64
#define NTOK    144
#define DIM     192
#define NH      6
#define HD      32
#define MROWS   (B_LON * NW * NTOK)   // 138240
#define QKV_N   (3 * DIM)             // 576
#define NBIAS   3312
#define RB      72             // rows per attention CTA (half a window)

// Scratch (allocation-free rule: __device__ globals)
__device__ float g_qkv[(size_t)B_LON * NW * NTOK * QKV_N];   // 318 MB
__device__ float g_att[(size_t)B_LON * NW * NTOK * DIM];     // 106 MB
__device__ float g_biasT[(size_t)NW * NH * NBIAS];           // 5 MB: [w*NH+h][idx]

// ---------------------------------------------------------------------------
__global__ void bias_transpose_kernel(const float* __restrict__ bias_table,
                                      float* __restrict__ biasT)
{
    int idx = blockIdx.x;          // 0..3311
    int wh  = threadIdx.x;         // 0..383
    biasT[(size_t)wh * NBIAS + idx] = bias_table[(size_t)idx * (NW * NH) + wh];
}

// ---------------------------------------------------------------------------
// tf32 + cp.async helpers
// ---------------------------------------------------------------------------
__device__ __forceinline__ uint32_t f2tf32(float f) {
    uint32_t u;
    asm("cvt.rna.tf32.f32 %0, %1;" : "=r"(u) : "f"(f));
    return u;
}

__device__ __forceinline__ void mma_tf32(float* c, const uint32_t* a,
                                         const uint32_t* b) {
    asm volatile(
        "mma.sync.aligned.m16n8k8.row.col.f32.tf32.tf32.f32 "
        "{%0,%1,%2,%3}, {%4,%5,%6,%7}, {%8,%9}, {%0,%1,%2,%3};"
        : "+f"(c[0]), "+f"(c[1]), "+f"(c[2]), "+f"(c[3])
        : "r"(a[0]), "r"(a[1]), "r"(a[2]), "r"(a[3]),
          "r"(b[0]), "r"(b[1]));
}

__device__ __forceinline__ void cp16(void* dst, const void* src) {
    uint32_t s = (uint32_t)__cvta_generic_to_shared(dst);
    asm volatile("cp.async.cg.shared.global [%0], [%1], 16;" :: "r"(s), "l"(src));
}
__device__ __forceinline__ void cp_commit() {
    asm volatile("cp.async.commit_group;");
}
template <int N> __device__ __forceinline__ void cp_wait() {
    asm volatile("cp.async.wait_group %0;" :: "n"(N));
}
__device__ __forceinline__ void cp_wait_all() {
    asm volatile("cp.async.wait_all;");
}

// ---------------------------------------------------------------------------
// tf32 tensor-core GEMM + bias, 4-stage cp.async ring, ONE sync per K-tile.
// (unchanged — profiled stable)
// ---------------------------------------------------------------------------
#define BM 128
#define BN 64
#define BK 16
#define AP 20
#define BP 72
#define NST 4
#define GEMM_SMEM_BYTES (NST * (BM * AP + BK * BP) * 4)

__global__ __launch_bounds__(256, 3) void gemm_tf32_kernel(
    const float* __restrict__ A, const float* __restrict__ B,
    const float* __restrict__ bias, float* __restrict__ C,
    int M, int N, int K)
{
    extern __shared__ float gsm[];
    float* As = gsm;                    // [NST][BM*AP]
    float* Bs = gsm + NST * BM * AP;    // [NST][BK*BP]

    const int tid  = threadIdx.x;
    const int lane = tid & 31;
    const int wid  = tid >> 5;
    const int wm   = wid & 3;
    const int wn   = wid >> 2;
    const int grp  = lane >> 2;
    const int tig  = lane & 3;

    const int m0 = blockIdx.y * BM;
    const int n0 = blockIdx.x * BN;

    const int ar = tid >> 1;
    const int ac = (tid & 1) * 8;
    const float* Ag = A + (size_t)(m0 + ar) * K + ac;
    const int bkr = tid >> 4;
    const int bnc = (tid & 15) * 4;
    const float* Bg = B + (size_t)bkr * N + n0 + bnc;

    float acc[2][4][4];
#pragma unroll
    for (int mi = 0; mi < 2; mi++)
#pragma unroll
        for (int ni = 0; ni < 4; ni++)
#pragma unroll
            for (int r = 0; r < 4; r++) acc[mi][ni][r] = 0.0f;

    const int T = K / BK;   // 12

#pragma unroll
    for (int p = 0; p < 2; p++) {
        const float* a = Ag + p * BK;
        cp16(&As[p * BM * AP + ar * AP + ac],     a);
        cp16(&As[p * BM * AP + ar * AP + ac + 4], a + 4);
        cp16(&Bs[p * BK * BP + bkr * BP + bnc],   Bg + (size_t)p * BK * N);
        cp_commit();
    }

    for (int t = 0; t < T; t++) {
        if (t + 2 < T) {
            const int nb = (t + 2) % NST;
            const float* a = Ag + (t + 2) * BK;
            cp16(&As[nb * BM * AP + ar * AP + ac],     a);
            cp16(&As[nb * BM * AP + ar * AP + ac + 4], a + 4);
            cp16(&Bs[nb * BK * BP + bkr * BP + bnc],
                 Bg + (size_t)(t + 2) * BK * N);
            cp_commit();
            cp_wait<2>();
        } else {
            cp_wait<0>();
        }
        __syncthreads();

        const float* Asb = As + (t % NST) * BM * AP;
        const float* Bsb = Bs + (t % NST) * BK * BP;
#pragma unroll
        for (int kc = 0; kc < BK; kc += 8) {
            uint32_t af[2][4], bf[4][2];
#pragma unroll
            for (int mi = 0; mi < 2; mi++) {
                int mb = wm * 32 + mi * 16 + grp;
                af[mi][0] = f2tf32(Asb[(mb)     * AP + kc + tig]);
                af[mi][1] = f2tf32(Asb[(mb + 8) * AP + kc + tig]);
                af[mi][2] = f2tf32(Asb[(mb)     * AP + kc + tig + 4]);
                af[mi][3] = f2tf32(Asb[(mb + 8) * AP + kc + tig + 4]);
            }
#pragma unroll
            for (int ni = 0; ni < 4; ni++) {
                int nb = wn * 32 + ni * 8 + grp;
                bf[ni][0] = f2tf32(Bsb[(kc + tig)     * BP + nb]);
                bf[ni][1] = f2tf32(Bsb[(kc + tig + 4) * BP + nb]);
            }
#pragma unroll
            for (int mi = 0; mi < 2; mi++)
#pragma unroll
                for (int ni = 0; ni < 4; ni++)
                    mma_tf32(acc[mi][ni], af[mi], bf[ni]);
        }
    }

#pragma unroll
    for (int mi = 0; mi < 2; mi++) {
        int row = m0 + wm * 32 + mi * 16 + grp;
#pragma unroll
        for (int ni = 0; ni < 4; ni++) {
            int col = n0 + wn * 32 + ni * 8 + 2 * tig;
            float2 bv = *(const float2*)(bias + col);
            float2 o0, o1;
            o0.x = acc[mi][ni][0] + bv.x;
            o0.y = acc[mi][ni][1] + bv.y;
            o1.x = acc[mi][ni][2] + bv.x;
            o1.y = acc[mi][ni][3] + bv.y;
            *(float2*)(C + (size_t)row * N + col)       = o0;
            *(float2*)(C + (size_t)(row + 8) * N + col) = o1;
        }
    }
}

// ---------------------------------------------------------------------------
// Fused attention, tensor-core QK^T and PV, pre-converted tf32 operands.
// GRID REORDER (this round): gridDim = (NH*2, NW, B_LON);
//   x = h*2+rb, y = w, z = b. The 12 CTAs sharing one (b,w) — same mask
// window and same k/v rows — are now CONSECUTIVE in launch order, so L2
// converts the 6x mask and 2x k/v redundancy into hits.
// idx = f(n) + g(m): f = 828*zi + 23*hi + wi ; g = 1656*zj + 138*hj - wj + 11
// smem 105.7 KB -> 2 CTAs/SM.
// ---------------------------------------------------------------------------
#define QP 36     // qS pitch
#define KP 36     // kS pitch
#define VP 148    // vT pitch
#define SP 148    // S pitch

#define SM_QS    0                       // [80][36] (rows 72..79 zero)
#define SM_KS    (SM_QS + 80 * QP)       // [144][36]
#define SM_VT    (SM_KS + NTOK * KP)     // [32][148] u32 tf32
#define SM_S     (SM_VT + 32 * VP)       // [72][148]
#define SM_BIAS  (SM_S + RB * SP)        // [3312] (also phantom S rows)
#define SM_RSUM  (SM_BIAS + NBIAS)       // [72]
#define SM_FI    (SM_RSUM + RB)          // [72] int
#define SM_GI    (SM_FI + RB)            // [144] int
#define ATT_SMEM_BYTES ((SM_GI + NTOK) * 4)

__global__ __launch_bounds__(256, 2) void attn_kernel(
    const float* __restrict__ qkv, const float* __restrict__ mask,
    const float* __restrict__ biasT, float* __restrict__ out)
{
    extern __shared__ float sm[];
    float*    qSf  = sm + SM_QS;
    float*    kSf  = sm + SM_KS;
    uint32_t* qSu  = (uint32_t*)qSf;
    uint32_t* kSu  = (uint32_t*)kSf;
    uint32_t* vT   = (uint32_t*)sm + SM_VT;
    float*    S    = sm + SM_S;
    uint32_t* Su   = (uint32_t*)S;
    float*    sbias= sm + SM_BIAS;
    float*    rsum = sm + SM_RSUM;
    int*      fI   = (int*)sm + SM_FI;
    int*      gI   = (int*)sm + SM_GI;

    // Grid: x = h*2+rb (12), y = w (64), z = b (15)
    const int h  = blockIdx.x >> 1;
    const int rb = blockIdx.x & 1;
    const int w  = blockIdx.y;
    const int b  = blockIdx.z;
    const int tid  = threadIdx.x;
    const int lane = tid & 31;
    const int wp   = tid >> 5;          // 8 warps
    const int grp  = lane >> 2;         // 0..7
    const int tig  = lane & 3;          // 0..3
    const int bw = b * NW + w;
    const int row0 = rb * RB;
    const float* base = qkv + (size_t)bw * NTOK * QKV_N;
    const float* mbase = mask + (size_t)bw * NTOK * NTOK;
    const float scale = 0.17677669529663687f;  // 1/sqrt(32)

    // ---- cp.async staging: q (local 72 rows), k (all), bias slice
    for (int idx = tid; idx < RB * 8; idx += 256) {
        int r = idx >> 3, c = (idx & 7) * 4;
        cp16(&qSf[r * QP + c],
             base + (size_t)(row0 + r) * QKV_N + h * HD + c);
    }
    for (int idx = tid; idx < NTOK * 8; idx += 256) {
        int r = idx >> 3, c = (idx & 7) * 4;
        cp16(&kSf[r * KP + c],
             base + (size_t)r * QKV_N + DIM + h * HD + c);
    }
    {
        const float* bsrc = biasT + (size_t)(w * NH + h) * NBIAS;
        for (int i = tid * 4; i < NBIAS; i += 1024)
            cp16(&sbias[i], bsrc + i);
    }
    cp_commit();

    // ---- v: register path (transpose + tf32 convert), overlaps cp.async
    for (int idx = tid; idx < NTOK * 8; idx += 256) {
        int n = idx >> 3, d = (idx & 7) * 4;
        float4 v4 = *(const float4*)(base + (size_t)n * QKV_N + 2 * DIM
                                     + h * HD + d);
        vT[(d + 0) * VP + n] = f2tf32(v4.x);
        vT[(d + 1) * VP + n] = f2tf32(v4.y);
        vT[(d + 2) * VP + n] = f2tf32(v4.z);
        vT[(d + 3) * VP + n] = f2tf32(v4.w);
    }
    // qS pad rows 72..79 zero
    for (int i = tid; i < 8 * QP; i += 256) qSf[RB * QP + i] = 0.0f;
    if (tid < RB) {
        int n = row0 + tid;
        int zi = n / 72, hi = (n / 12) % 6, wi = n % 12;
        fI[tid] = 828 * zi + 23 * hi + wi;
    }
    if (tid < NTOK) {
        int zj = tid / 72, hj = (tid / 12) % 6, wj = tid % 12;
        gI[tid] = 1656 * zj + 138 * hj - wj + 11;
    }
    cp_wait_all();
    __syncthreads();

    // ---- Repack: q (x scale) and k fp32 -> tf32 bits, in place.
    for (int i = tid; i < 80 * QP; i += 256) qSu[i] = f2tf32(qSf[i] * scale);
    for (int i = tid; i < NTOK * KP; i += 256) kSu[i] = f2tf32(kSf[i]);
    __syncthreads();

    // ---- Phase 2: S = (scaled q) k^T + bias via mma.
    // m-block outer (a-frags hoisted), rotated n-tile round-robin.
#pragma unroll
    for (int mb = 0; mb < 5; mb++) {
        uint32_t a[4][4];
#pragma unroll
        for (int kc8 = 0; kc8 < 4; kc8++) {
            int ab = (mb * 16 + grp) * QP + kc8 * 8 + tig;
            a[kc8][0] = qSu[ab];
            a[kc8][1] = qSu[ab + 8 * QP];
            a[kc8][2] = qSu[ab + 4];
            a[kc8][3] = qSu[ab + 8 * QP + 4];
        }
        int start = (wp + mb) & 7;           // rotate for load balance
        for (int nt = start; nt < 18; nt += 8) {
            float c[4] = {0.0f, 0.0f, 0.0f, 0.0f};
#pragma unroll
            for (int kc8 = 0; kc8 < 4; kc8++) {
                uint32_t bfr[2];
                int bb = (nt * 8 + grp) * KP + kc8 * 8 + tig;
                bfr[0] = kSu[bb];
                bfr[1] = kSu[bb + 4];
                mma_tf32(c, a[kc8], bfr);
            }
            int col = nt * 8 + 2 * tig;
            int g0 = gI[col], g1 = gI[col + 1];
#pragma unroll
            for (int p = 0; p < 2; p++) {
                int r = mb * 16 + grp + p * 8;
                if (r < RB) {
                    int f = fI[r];
                    float* sr = S + r * SP + col;
                    sr[0] = c[2 * p]     + sbias[f + g0];
                    sr[1] = c[2 * p + 1] + sbias[f + g1];
                }
            }
        }
    }
    __syncthreads();

    // ---- Phase 3: softmax with mask from gmem; store P as tf32 bits.
    {
#pragma unroll
        for (int i = 0; i < 9; i++) {
            int r = wp * 9 + i;
            float* row = S + r * SP;
            const float* mrow = mbase + (size_t)(row0 + r) * NTOK;
            float v0 = row[lane]       + mrow[lane];
            float v1 = row[lane + 32]  + mrow[lane + 32];
            float v2 = row[lane + 64]  + mrow[lane + 64];
            float v3 = row[lane + 96]  + mrow[lane + 96];
            float v4 = (lane < 16) ? row[lane + 128] + mrow[lane + 128]
                                   : -1e30f;
            float mx = fmaxf(fmaxf(fmaxf(v0, v1), fmaxf(v2, v3)), v4);
#pragma unroll
            for (int off = 16; off > 0; off >>= 1)
                mx = fmaxf(mx, __shfl_xor_sync(0xffffffffu, mx, off));
            float e0 = __expf(v0 - mx);
            float e1 = __expf(v1 - mx);
            float e2 = __expf(v2 - mx);
            float e3 = __expf(v3 - mx);
            float e4 = (lane < 16) ? __expf(v4 - mx) : 0.0f;
            uint32_t* rowu = (uint32_t*)row;
            rowu[lane]       = f2tf32(e0);
            rowu[lane + 32]  = f2tf32(e1);
            rowu[lane + 64]  = f2tf32(e2);
            rowu[lane + 96]  = f2tf32(e3);
            if (lane < 16) rowu[lane + 128] = f2tf32(e4);
            float s = (e0 + e1) + (e2 + e3) + e4;
#pragma unroll
            for (int off = 16; off > 0; off >>= 1)
                s += __shfl_xor_sync(0xffffffffu, s, off);
            if (lane == 0) rsum[r] = 1.0f / s;
        }
    }
    __syncthreads();

    // ---- Phase 4: O = P v via mma. Warp wp: fixed n-tile (wp&3),
    // m-blocks (wp>>2), +2, +4. v-frags hoisted (36 regs).
    // Phantom A rows 72..79 read the bias region: in-bounds garbage,
    // contaminates only guarded (discarded) output rows.
    {
        const int nt = wp & 3;
        uint32_t bf[18][2];
#pragma unroll
        for (int kc8 = 0; kc8 < 18; kc8++) {
            int bb = (nt * 8 + grp) * VP + kc8 * 8 + tig;
            bf[kc8][0] = vT[bb];
            bf[kc8][1] = vT[bb + 4];
        }
        float* ob0 = out + (size_t)bw * NTOK * DIM + h * HD;
        for (int mb = (wp >> 2); mb < 5; mb += 2) {
            float c[4] = {0.0f, 0.0f, 0.0f, 0.0f};
#pragma unroll
            for (int kc8 = 0; kc8 < 18; kc8++) {
                uint32_t a[4];
                int ab = (mb * 16 + grp) * SP + kc8 * 8 + tig;
                a[0] = Su[ab];
                a[1] = Su[ab + 8 * SP];
                a[2] = Su[ab + 4];
                a[3] = Su[ab + 8 * SP + 4];
                mma_tf32(c, a, bf[kc8]);
            }
            int col = nt * 8 + 2 * tig;
#pragma unroll
            for (int p = 0; p < 2; p++) {
                int r = mb * 16 + grp + p * 8;
                if (r < RB) {
                    float rs = rsum[r];
                    float2 o;
                    o.x = c[2 * p] * rs;
                    o.y = c[2 * p + 1] * rs;
                    *(float2*)(ob0 + (size_t)(row0 + r) * DIM + col) = o;
                }
            }
        }
    }
}

// ---------------------------------------------------------------------------
extern "C" void kernel_launch(void* const* d_in, const int* in_sizes, int n_in,
                              void* d_out, int out_size)
{
    const float* x          = (const float*)d_in[0];
    const float* mask       = (const float*)d_in[1];
    const float* qkv_w      = (const float*)d_in[2];
    const float* qkv_b      = (const float*)d_in[3];
    const float* proj_w     = (const float*)d_in[4];
    const float* proj_b     = (const float*)d_in[5];
    const float* bias_table = (const float*)d_in[6];
    float* out = (float*)d_out;

    float *qkv_s, *att_s, *biasT_s;
    cudaGetSymbolAddress((void**)&qkv_s, g_qkv);
    cudaGetSymbolAddress((void**)&att_s, g_att);
    cudaGetSymbolAddress((void**)&biasT_s, g_biasT);

    cudaFuncSetAttribute(gemm_tf32_kernel,
                         cudaFuncAttributeMaxDynamicSharedMemorySize,
                         GEMM_SMEM_BYTES);
    cudaFuncSetAttribute(attn_kernel,
                         cudaFuncAttributeMaxDynamicSharedMemorySize,
                         ATT_SMEM_BYTES);

    // 0) Bias table pre-transpose (tiny)
    bias_transpose_kernel<<<NBIAS, NW * NH>>>(bias_table, biasT_s);

    // 1) QKV projection: (138240 x 192) @ (192 x 576) + b   [tf32 tensor]
    gemm_tf32_kernel<<<dim3(QKV_N / BN, MROWS / BM), 256, GEMM_SMEM_BYTES>>>(
        x, qkv_w, qkv_b, qkv_s, MROWS, QKV_N, DIM);

    // 2) Fused windowed attention. Grid x=(h,rb) so CTAs sharing (b,w)
    //    — same mask + k/v — are launch-adjacent (L2 reuse).
    attn_kernel<<<dim3(NH * 2, NW, B_LON), 256, ATT_SMEM_BYTES>>>(
        qkv_s, mask, biasT_s, att_s);

    // 3) Output projection: (138240 x 192) @ (192 x 192) + b [tf32 tensor]
    gemm_tf32_kernel<<<dim3(DIM / BN, MROWS / BM), 256, GEMM_SMEM_BYTES>>>(
        att_s, proj_w, proj_b, out, MROWS, DIM, DIM);
}

// round 17
// speedup vs baseline: 1.2575x; 1.1341x over previous
#include <cuda_runtime.h>
#include <cuda_bf16.h>
#include <cstdint>

// Problem constants
#define B_LON   15
#define NW      64
#define NTOK    144
#define DIM     192
#define NH      6
#define HD      32
#define MROWS   (B_LON * NW * NTOK)   // 138240
#define QKV_N   (3 * DIM)             // 576
#define NBIAS   3312
#define RB      72             // rows per attention CTA (half a window)

// Scratch (allocation-free rule: __device__ globals)
__device__ float g_qkv[(size_t)B_LON * NW * NTOK * QKV_N];   // 318 MB
__device__ float g_att[(size_t)B_LON * NW * NTOK * DIM];     // 106 MB
__device__ float g_biasT[(size_t)NW * NH * NBIAS];           // 5 MB: [w*NH+h][idx]

// ---------------------------------------------------------------------------
__global__ void bias_transpose_kernel(const float* __restrict__ bias_table,
                                      float* __restrict__ biasT)
{
    int idx = blockIdx.x;          // 0..3311
    int wh  = threadIdx.x;         // 0..383
    biasT[(size_t)wh * NBIAS + idx] = bias_table[(size_t)idx * (NW * NH) + wh];
}

// ---------------------------------------------------------------------------
// tf32 + cp.async helpers
// ---------------------------------------------------------------------------
__device__ __forceinline__ uint32_t f2tf32(float f) {
    uint32_t u;
    asm("cvt.rna.tf32.f32 %0, %1;" : "=r"(u) : "f"(f));
    return u;
}

__device__ __forceinline__ void mma_tf32(float* c, const uint32_t* a,
                                         const uint32_t* b) {
    asm volatile(
        "mma.sync.aligned.m16n8k8.row.col.f32.tf32.tf32.f32 "
        "{%0,%1,%2,%3}, {%4,%5,%6,%7}, {%8,%9}, {%0,%1,%2,%3};"
        : "+f"(c[0]), "+f"(c[1]), "+f"(c[2]), "+f"(c[3])
        : "r"(a[0]), "r"(a[1]), "r"(a[2]), "r"(a[3]),
          "r"(b[0]), "r"(b[1]));
}

__device__ __forceinline__ void cp16(void* dst, const void* src) {
    uint32_t s = (uint32_t)__cvta_generic_to_shared(dst);
    asm volatile("cp.async.cg.shared.global [%0], [%1], 16;" :: "r"(s), "l"(src));
}
__device__ __forceinline__ void cp_commit() {
    asm volatile("cp.async.commit_group;");
}
template <int N> __device__ __forceinline__ void cp_wait() {
    asm volatile("cp.async.wait_group %0;" :: "n"(N));
}
__device__ __forceinline__ void cp_wait_all() {
    asm volatile("cp.async.wait_all;");
}

// ---------------------------------------------------------------------------
// tf32 tensor-core GEMM + bias, 4-stage cp.async ring, ONE sync per K-tile.
// (unchanged — profiled stable)
// ---------------------------------------------------------------------------
#define BM 128
#define BN 64
#define BK 16
#define AP 20
#define BP 72
#define NST 4
#define GEMM_SMEM_BYTES (NST * (BM * AP + BK * BP) * 4)

__global__ __launch_bounds__(256, 3) void gemm_tf32_kernel(
    const float* __restrict__ A, const float* __restrict__ B,
    const float* __restrict__ bias, float* __restrict__ C,
    int M, int N, int K)
{
    extern __shared__ float gsm[];
    float* As = gsm;                    // [NST][BM*AP]
    float* Bs = gsm + NST * BM * AP;    // [NST][BK*BP]

    const int tid  = threadIdx.x;
    const int lane = tid & 31;
    const int wid  = tid >> 5;
    const int wm   = wid & 3;
    const int wn   = wid >> 2;
    const int grp  = lane >> 2;
    const int tig  = lane & 3;

    const int m0 = blockIdx.y * BM;
    const int n0 = blockIdx.x * BN;

    const int ar = tid >> 1;
    const int ac = (tid & 1) * 8;
    const float* Ag = A + (size_t)(m0 + ar) * K + ac;
    const int bkr = tid >> 4;
    const int bnc = (tid & 15) * 4;
    const float* Bg = B + (size_t)bkr * N + n0 + bnc;

    float acc[2][4][4];
#pragma unroll
    for (int mi = 0; mi < 2; mi++)
#pragma unroll
        for (int ni = 0; ni < 4; ni++)
#pragma unroll
            for (int r = 0; r < 4; r++) acc[mi][ni][r] = 0.0f;

    const int T = K / BK;   // 12

#pragma unroll
    for (int p = 0; p < 2; p++) {
        const float* a = Ag + p * BK;
        cp16(&As[p * BM * AP + ar * AP + ac],     a);
        cp16(&As[p * BM * AP + ar * AP + ac + 4], a + 4);
        cp16(&Bs[p * BK * BP + bkr * BP + bnc],   Bg + (size_t)p * BK * N);
        cp_commit();
    }

    for (int t = 0; t < T; t++) {
        if (t + 2 < T) {
            const int nb = (t + 2) % NST;
            const float* a = Ag + (t + 2) * BK;
            cp16(&As[nb * BM * AP + ar * AP + ac],     a);
            cp16(&As[nb * BM * AP + ar * AP + ac + 4], a + 4);
            cp16(&Bs[nb * BK * BP + bkr * BP + bnc],
                 Bg + (size_t)(t + 2) * BK * N);
            cp_commit();
            cp_wait<2>();
        } else {
            cp_wait<0>();
        }
        __syncthreads();

        const float* Asb = As + (t % NST) * BM * AP;
        const float* Bsb = Bs + (t % NST) * BK * BP;
#pragma unroll
        for (int kc = 0; kc < BK; kc += 8) {
            uint32_t af[2][4], bf[4][2];
#pragma unroll
            for (int mi = 0; mi < 2; mi++) {
                int mb = wm * 32 + mi * 16 + grp;
                af[mi][0] = f2tf32(Asb[(mb)     * AP + kc + tig]);
                af[mi][1] = f2tf32(Asb[(mb + 8) * AP + kc + tig]);
                af[mi][2] = f2tf32(Asb[(mb)     * AP + kc + tig + 4]);
                af[mi][3] = f2tf32(Asb[(mb + 8) * AP + kc + tig + 4]);
            }
#pragma unroll
            for (int ni = 0; ni < 4; ni++) {
                int nb = wn * 32 + ni * 8 + grp;
                bf[ni][0] = f2tf32(Bsb[(kc + tig)     * BP + nb]);
                bf[ni][1] = f2tf32(Bsb[(kc + tig + 4) * BP + nb]);
            }
#pragma unroll
            for (int mi = 0; mi < 2; mi++)
#pragma unroll
                for (int ni = 0; ni < 4; ni++)
                    mma_tf32(acc[mi][ni], af[mi], bf[ni]);
        }
    }

#pragma unroll
    for (int mi = 0; mi < 2; mi++) {
        int row = m0 + wm * 32 + mi * 16 + grp;
#pragma unroll
        for (int ni = 0; ni < 4; ni++) {
            int col = n0 + wn * 32 + ni * 8 + 2 * tig;
            float2 bv = *(const float2*)(bias + col);
            float2 o0, o1;
            o0.x = acc[mi][ni][0] + bv.x;
            o0.y = acc[mi][ni][1] + bv.y;
            o1.x = acc[mi][ni][2] + bv.x;
            o1.y = acc[mi][ni][3] + bv.y;
            *(float2*)(C + (size_t)row * N + col)       = o0;
            *(float2*)(C + (size_t)(row + 8) * N + col) = o1;
        }
    }
}

// ---------------------------------------------------------------------------
// Fused attention, tensor-core QK^T and PV, 3 CTAs/SM (74.25 KB smem).
// CTA = (h,rb | w | b). Changes this round:
//  - bias slice NOT staged: phase-2 epilogue gathers from L2-resident biasT
//  - v staged AFTER phase 2 into the dead qS/kS region (cp.async overlapped
//    with softmax), natural [token][d] layout pitch 40 (conflict-free frags)
//  - phase-4 phantom A rows clamped to 71 (outputs store-guarded)
// idx = f(n) + g(m): f = 828*zi + 23*hi + wi ; g = 1656*zj + 138*hj - wj + 11
// ---------------------------------------------------------------------------
#define QP 36     // qS pitch
#define KP 36     // kS pitch
#define VPP 40    // vS pitch (natural [token][d]; bank 8*tig+grp, clean)
#define SP 148    // S pitch

#define SM_QS    0                       // [80][36] (rows 72..79 zero)
#define SM_KS    (SM_QS + 80 * QP)       // [144][36]          (end 8064)
#define SM_VS    0                       // [144][40] OVERLAYS qS/kS (5760<8064)
#define SM_S     (SM_KS + NTOK * KP)     // [72][148] = 8064..18720
#define SM_RSUM  (SM_S + RB * SP)        // [72]
#define SM_FI    (SM_RSUM + RB)          // [72] int
#define SM_GI    (SM_FI + RB)            // [144] int
#define ATT_SMEM_BYTES ((SM_GI + NTOK) * 4)   // 76032 B = 74.25 KB

__global__ __launch_bounds__(256, 3) void attn_kernel(
    const float* __restrict__ qkv, const float* __restrict__ mask,
    const float* __restrict__ biasT, float* __restrict__ out)
{
    extern __shared__ float sm[];
    float*    qSf  = sm + SM_QS;
    float*    kSf  = sm + SM_KS;
    uint32_t* qSu  = (uint32_t*)qSf;
    uint32_t* kSu  = (uint32_t*)kSf;
    float*    vSf  = sm + SM_VS;          // valid only after phase 2
    uint32_t* vSu  = (uint32_t*)vSf;
    float*    S    = sm + SM_S;
    uint32_t* Su   = (uint32_t*)S;
    float*    rsum = sm + SM_RSUM;
    int*      fI   = (int*)sm + SM_FI;
    int*      gI   = (int*)sm + SM_GI;

    // Grid: x = h*2+rb (12), y = w (64), z = b (15)
    const int h  = blockIdx.x >> 1;
    const int rb = blockIdx.x & 1;
    const int w  = blockIdx.y;
    const int b  = blockIdx.z;
    const int tid  = threadIdx.x;
    const int lane = tid & 31;
    const int wp   = tid >> 5;          // 8 warps
    const int grp  = lane >> 2;         // 0..7
    const int tig  = lane & 3;          // 0..3
    const int bw = b * NW + w;
    const int row0 = rb * RB;
    const float* base = qkv + (size_t)bw * NTOK * QKV_N;
    const float* mbase = mask + (size_t)bw * NTOK * NTOK;
    const float* bT = biasT + (size_t)(w * NH + h) * NBIAS;
    const float scale = 0.17677669529663687f;  // 1/sqrt(32)

    // ---- cp.async staging: q (local 72 rows), k (all 144 rows)
    for (int idx = tid; idx < RB * 8; idx += 256) {
        int r = idx >> 3, c = (idx & 7) * 4;
        cp16(&qSf[r * QP + c],
             base + (size_t)(row0 + r) * QKV_N + h * HD + c);
    }
    for (int idx = tid; idx < NTOK * 8; idx += 256) {
        int r = idx >> 3, c = (idx & 7) * 4;
        cp16(&kSf[r * KP + c],
             base + (size_t)r * QKV_N + DIM + h * HD + c);
    }
    cp_commit();

    // Index tables (overlap cp.async)
    if (tid < RB) {
        int n = row0 + tid;
        int zi = n / 72, hi = (n / 12) % 6, wi = n % 12;
        fI[tid] = 828 * zi + 23 * hi + wi;
    }
    if (tid < NTOK) {
        int zj = tid / 72, hj = (tid / 12) % 6, wj = tid % 12;
        gI[tid] = 1656 * zj + 138 * hj - wj + 11;
    }
    cp_wait_all();
    __syncthreads();

    // ---- Repack: q (x scale) and k fp32 -> tf32 bits, in place.
    // qS pad rows 72..79 contain stale data; zero them via the repack range.
    for (int i = tid; i < RB * QP; i += 256) qSu[i] = f2tf32(qSf[i] * scale);
    for (int i = tid; i < 8 * QP; i += 256)  qSu[RB * QP + i] = 0;
    for (int i = tid; i < NTOK * KP; i += 256) kSu[i] = f2tf32(kSf[i]);
    __syncthreads();

    // ---- Phase 2: S = (scaled q) k^T + bias(L2 gather) via mma.
#pragma unroll
    for (int mb = 0; mb < 5; mb++) {
        uint32_t a[4][4];
#pragma unroll
        for (int kc8 = 0; kc8 < 4; kc8++) {
            int ab = (mb * 16 + grp) * QP + kc8 * 8 + tig;
            a[kc8][0] = qSu[ab];
            a[kc8][1] = qSu[ab + 8 * QP];
            a[kc8][2] = qSu[ab + 4];
            a[kc8][3] = qSu[ab + 8 * QP + 4];
        }
        int start = (wp + mb) & 7;           // rotate for load balance
        for (int nt = start; nt < 18; nt += 8) {
            float c[4] = {0.0f, 0.0f, 0.0f, 0.0f};
#pragma unroll
            for (int kc8 = 0; kc8 < 4; kc8++) {
                uint32_t bfr[2];
                int bb = (nt * 8 + grp) * KP + kc8 * 8 + tig;
                bfr[0] = kSu[bb];
                bfr[1] = kSu[bb + 4];
                mma_tf32(c, a[kc8], bfr);
            }
            int col = nt * 8 + 2 * tig;
            int g0 = gI[col], g1 = gI[col + 1];
#pragma unroll
            for (int p = 0; p < 2; p++) {
                int r = mb * 16 + grp + p * 8;
                if (r < RB) {
                    int f = fI[r];
                    float* sr = S + r * SP + col;
                    sr[0] = c[2 * p]     + __ldg(bT + f + g0);
                    sr[1] = c[2 * p + 1] + __ldg(bT + f + g1);
                }
            }
        }
    }
    __syncthreads();   // S complete; qS/kS now dead

    // ---- Stage v into the dead qS/kS region (overlaps softmax below).
    // Natural layout vS[token][d], pitch 40.
    for (int idx = tid; idx < NTOK * 8; idx += 256) {
        int r = idx >> 3, c = (idx & 7) * 4;
        cp16(&vSf[r * VPP + c],
             base + (size_t)r * QKV_N + 2 * DIM + h * HD + c);
    }
    cp_commit();

    // ---- Phase 3: softmax with mask from gmem; store P as tf32 bits.
    {
#pragma unroll
        for (int i = 0; i < 9; i++) {
            int r = wp * 9 + i;
            float* row = S + r * SP;
            const float* mrow = mbase + (size_t)(row0 + r) * NTOK;
            float v0 = row[lane]       + mrow[lane];
            float v1 = row[lane + 32]  + mrow[lane + 32];
            float v2 = row[lane + 64]  + mrow[lane + 64];
            float v3 = row[lane + 96]  + mrow[lane + 96];
            float v4 = (lane < 16) ? row[lane + 128] + mrow[lane + 128]
                                   : -1e30f;
            float mx = fmaxf(fmaxf(fmaxf(v0, v1), fmaxf(v2, v3)), v4);
#pragma unroll
            for (int off = 16; off > 0; off >>= 1)
                mx = fmaxf(mx, __shfl_xor_sync(0xffffffffu, mx, off));
            float e0 = __expf(v0 - mx);
            float e1 = __expf(v1 - mx);
            float e2 = __expf(v2 - mx);
            float e3 = __expf(v3 - mx);
            float e4 = (lane < 16) ? __expf(v4 - mx) : 0.0f;
            uint32_t* rowu = (uint32_t*)row;
            rowu[lane]       = f2tf32(e0);
            rowu[lane + 32]  = f2tf32(e1);
            rowu[lane + 64]  = f2tf32(e2);
            rowu[lane + 96]  = f2tf32(e3);
            if (lane < 16) rowu[lane + 128] = f2tf32(e4);
            float s = (e0 + e1) + (e2 + e3) + e4;
#pragma unroll
            for (int off = 16; off > 0; off >>= 1)
                s += __shfl_xor_sync(0xffffffffu, s, off);
            if (lane == 0) rsum[r] = 1.0f / s;
        }
    }
    cp_wait_all();      // v landed
    __syncthreads();    // softmax + v both visible

    // ---- Repack v fp32 -> tf32 in place (cols 0..31 only).
    for (int i = tid; i < NTOK * HD; i += 256) {
        int r = i >> 5, c = i & 31;
        vSu[r * VPP + c] = f2tf32(vSf[r * VPP + c]);
    }
    __syncthreads();

    // ---- Phase 4: O = P v via mma. Warp wp: fixed n-tile (wp&3),
    // m-blocks (wp>>2), +2, +4. v-frags hoisted (36 regs).
    // Phantom A rows (>=72) clamped to 71; their outputs are store-guarded.
    {
        const int nt = wp & 3;
        uint32_t bf[18][2];
#pragma unroll
        for (int kc8 = 0; kc8 < 18; kc8++) {
            int bb = (kc8 * 8 + tig) * VPP + nt * 8 + grp;
            bf[kc8][0] = vSu[bb];
            bf[kc8][1] = vSu[bb + 4 * VPP];
        }
        float* ob0 = out + (size_t)bw * NTOK * DIM + h * HD;
        for (int mb = (wp >> 2); mb < 5; mb += 2) {
            int r0 = mb * 16 + grp;
            int r1 = r0 + 8;
            int r1c = (r1 < RB) ? r1 : (RB - 1);   // clamp phantom rows
            float c[4] = {0.0f, 0.0f, 0.0f, 0.0f};
#pragma unroll
            for (int kc8 = 0; kc8 < 18; kc8++) {
                uint32_t a[4];
                int ab0 = r0  * SP + kc8 * 8 + tig;
                int ab1 = r1c * SP + kc8 * 8 + tig;
                a[0] = Su[ab0];
                a[1] = Su[ab1];
                a[2] = Su[ab0 + 4];
                a[3] = Su[ab1 + 4];
                mma_tf32(c, a, bf[kc8]);
            }
            int col = nt * 8 + 2 * tig;
#pragma unroll
            for (int p = 0; p < 2; p++) {
                int r = mb * 16 + grp + p * 8;
                if (r < RB) {
                    float rs = rsum[r];
                    float2 o;
                    o.x = c[2 * p] * rs;
                    o.y = c[2 * p + 1] * rs;
                    *(float2*)(ob0 + (size_t)(row0 + r) * DIM + col) = o;
                }
            }
        }
    }
}

// ---------------------------------------------------------------------------
extern "C" void kernel_launch(void* const* d_in, const int* in_sizes, int n_in,
                              void* d_out, int out_size)
{
    const float* x          = (const float*)d_in[0];
    const float* mask       = (const float*)d_in[1];
    const float* qkv_w      = (const float*)d_in[2];
    const float* qkv_b      = (const float*)d_in[3];
    const float* proj_w     = (const float*)d_in[4];
    const float* proj_b     = (const float*)d_in[5];
    const float* bias_table = (const float*)d_in[6];
    float* out = (float*)d_out;

    float *qkv_s, *att_s, *biasT_s;
    cudaGetSymbolAddress((void**)&qkv_s, g_qkv);
    cudaGetSymbolAddress((void**)&att_s, g_att);
    cudaGetSymbolAddress((void**)&biasT_s, g_biasT);

    cudaFuncSetAttribute(gemm_tf32_kernel,
                         cudaFuncAttributeMaxDynamicSharedMemorySize,
                         GEMM_SMEM_BYTES);
    cudaFuncSetAttribute(attn_kernel,
                         cudaFuncAttributeMaxDynamicSharedMemorySize,
                         ATT_SMEM_BYTES);

    // 0) Bias table pre-transpose (tiny)
    bias_transpose_kernel<<<NBIAS, NW * NH>>>(bias_table, biasT_s);

    // 1) QKV projection: (138240 x 192) @ (192 x 576) + b   [tf32 tensor]
    gemm_tf32_kernel<<<dim3(QKV_N / BN, MROWS / BM), 256, GEMM_SMEM_BYTES>>>(
        x, qkv_w, qkv_b, qkv_s, MROWS, QKV_N, DIM);

    // 2) Fused windowed attention. Grid x=(h,rb) so CTAs sharing (b,w)
    //    — same mask + k/v — are launch-adjacent (L2 reuse). 3 CTAs/SM.
    attn_kernel<<<dim3(NH * 2, NW, B_LON), 256, ATT_SMEM_BYTES>>>(
        qkv_s, mask, biasT_s, att_s);

    // 3) Output projection: (138240 x 192) @ (192 x 192) + b [tf32 tensor]
    gemm_tf32_kernel<<<dim3(DIM / BN, MROWS / BM), 256, GEMM_SMEM_BYTES>>>(
        att_s, proj_w, proj_b, out, MROWS, DIM, DIM);
}